// round 10
// baseline (speedup 1.0000x reference)
#include <cuda_runtime.h>

// YOLO-style detection loss — label rows streamed into smem, coalesced.
// preds:  (n, 1470) f32  [pcls 980 | pconf 98 | pbox 392]
// labels: (n, 1225) f32  per cell (25 floats): [flag | 20 cls | 4 box]

#define L_CELLS 49
#define ROW_P 1470
#define ROW_L 1225
#define NOOBJ_W 0.5f
#define OBJ_W 0.5f
#define CLS_W 0.5f
#define COORD_W 2.5f

#define THREADS 256
#define RPB 8                          // rows per block
#define CPB (RPB * L_CELLS)            // 392 cells per block
#define NWARPS (THREADS / 32)
#define NITER 2                        // ceil(392/256)
#define MAX_BLOCKS 16384

__device__ double   g_partials[MAX_BLOCKS];
__device__ unsigned g_counter = 0;     // self-wrapping; replay-safe

__device__ __forceinline__ float obj_cell_loss(
    const float* __restrict__ preds,
    const float* __restrict__ s_lab,
    const float* __restrict__ s_conf,
    int row0, int cellLocal)
{
    int r = cellLocal / L_CELLS;
    int l = cellLocal - r * L_CELLS;
    const float* la = s_lab + r * ROW_L + 25 * l;   // smem, gcd(25,32)=1
    const float* p  = preds + (size_t)(row0 + r) * ROW_P;

    float pcx = s_conf[r * 2 * L_CELLS + 2 * l];
    float pcy = s_conf[r * 2 * L_CELLS + 2 * l + 1];

    // ---- predicted boxes (4 f2, aligned: 1078+8l on even row base) ----
    const float* pb = p + 1078 + l * 8;
    float2 b01 = __ldg(reinterpret_cast<const float2*>(pb + 0));
    float2 b23 = __ldg(reinterpret_cast<const float2*>(pb + 2));
    float2 b45 = __ldg(reinterpret_cast<const float2*>(pb + 4));
    float2 b67 = __ldg(reinterpret_cast<const float2*>(pb + 6));

    // ---- class loss: pcls from gmem (10 f2), labels from smem ----
    const float* pcl = p + l * 20;
    float cls = 0.0f;
    #pragma unroll
    for (int c = 0; c < 20; c += 2) {
        float2 pv = __ldg(reinterpret_cast<const float2*>(pcl + c));
        float d0 = la[1 + c] - pv.x;
        float d1 = la[2 + c] - pv.y;
        cls += d0 * d0 + d1 * d1;
    }
    cls *= CLS_W;

    float tb0 = la[21], tb1 = la[22], tb2 = la[23], tb3 = la[24];

    // transformed: o = [x/S, y/S, w^2, h^2]; t = [x/S, y/S, w, h]
    float o0x = b01.x * (1.0f / 7.0f), o0y = b01.y * (1.0f / 7.0f);
    float o0w = b23.x * b23.x,         o0h = b23.y * b23.y;
    float o1x = b45.x * (1.0f / 7.0f), o1y = b45.y * (1.0f / 7.0f);
    float o1w = b67.x * b67.x,         o1h = b67.y * b67.y;
    float tx = tb0 * (1.0f / 7.0f), ty = tb1 * (1.0f / 7.0f);
    float tw = tb2, th = tb3;

    float iou0, iou1, r0, r1;
    {
        float left   = fmaxf(tx - 0.5f * tw, o0x - 0.5f * o0w);
        float right  = fminf(tx + 0.5f * tw, o0x + 0.5f * o0w);
        float top    = fmaxf(ty - 0.5f * th, o0y - 0.5f * o0h);
        float bottom = fminf(ty + 0.5f * th, o0y + 0.5f * o0h);
        float w = right - left, h = bottom - top;
        bool invalid = (w < 0.0f) || (h < 0.0f);
        float inter = invalid ? 0.0f : w * h;
        float uni = tw * th + o0w * o0h - inter;
        iou0 = invalid ? 0.0f : inter / fmaxf(uni, 1e-12f);
        float d0 = tx - o0x, d1 = ty - o0y, d2 = tw - o0w, d3 = th - o0h;
        r0 = d0 * d0 + d1 * d1 + d2 * d2 + d3 * d3;
    }
    {
        float left   = fmaxf(tx - 0.5f * tw, o1x - 0.5f * o1w);
        float right  = fminf(tx + 0.5f * tw, o1x + 0.5f * o1w);
        float top    = fmaxf(ty - 0.5f * th, o1y - 0.5f * o1h);
        float bottom = fminf(ty + 0.5f * th, o1y + 0.5f * o1h);
        float w = right - left, h = bottom - top;
        bool invalid = (w < 0.0f) || (h < 0.0f);
        float inter = invalid ? 0.0f : w * h;
        float uni = tw * th + o1w * o1h - inter;
        iou1 = invalid ? 0.0f : inter / fmaxf(uni, 1e-12f);
        float d0 = tx - o1x, d1 = ty - o1y, d2 = tw - o1w, d3 = th - o1h;
        r1 = d0 * d0 + d1 * d1 + d2 * d2 + d3 * d3;
    }

    // argmax/argmin first-index tie semantics
    float miou = fmaxf(iou0, iou1);
    int best = (miou > 0.0f) ? ((iou1 > iou0) ? 1 : 0)
                             : ((r1 < r0) ? 1 : 0);

    float best_iou  = best ? iou1 : iou0;
    float conf_best = best ? pcy : pcx;
    float dcb = best_iou - conf_best;
    // correction vs unconditional NOOBJ*(cx^2+cy^2) base term
    float conf_corr = OBJ_W * dcb * dcb - NOOBJ_W * conf_best * conf_best;

    float pbx = best ? b45.x : b01.x;
    float pby = best ? b45.y : b01.y;
    float pbw = best ? b67.x : b23.x;
    float pbh = best ? b67.y : b23.y;
    float st2 = sqrtf(tb2), st3 = sqrtf(tb3);
    float e0 = tb0 - pbx, e1 = tb1 - pby;
    float e2 = st2 - pbw, e3 = st3 - pbh;
    float coord = COORD_W * (e0 * e0 + e1 * e1 + e2 * e2 + e3 * e3);

    return conf_corr + cls + coord;
}

__global__ void __launch_bounds__(THREADS) yolo_loss_kernel(
    const float* __restrict__ preds,
    const float* __restrict__ labels,
    int n,                                // number of rows
    float* __restrict__ out)
{
    __shared__ float  s_lab[RPB * ROW_L];            // 9800 f = 39.2 KB
    __shared__ float  s_conf[RPB * 2 * L_CELLS];     //  784 f =  3.1 KB
    __shared__ double s_red[NWARPS];
    __shared__ bool   s_last;

    const int tid  = threadIdx.x;
    const int lane = tid & 31;
    const int wid  = tid >> 5;
    const int row0  = blockIdx.x * RPB;
    const int nrows = min(RPB, n - row0);
    const int ncell = nrows * L_CELLS;

    // ===== stage labels: fully coalesced float2 stream ======================
    {
        int nfl = nrows * ROW_L;                      // even (1225*even? 1225*8=9800)
        const float2* src = reinterpret_cast<const float2*>(
            labels + (size_t)row0 * ROW_L);           // row0*1225 even (row0 mult of 8)
        int nf2 = nfl >> 1;
        for (int f = tid; f < nf2; f += THREADS) {
            float2 v = __ldg(src + f);
            s_lab[2 * f]     = v.x;
            s_lab[2 * f + 1] = v.y;
        }
        if ((nfl & 1) && tid == 0)
            s_lab[nfl - 1] = __ldg(labels + (size_t)row0 * ROW_L + nfl - 1);
    }
    // ===== stage pconf: coalesced per-row float2 ============================
    for (int f = tid; f < nrows * L_CELLS; f += THREADS) {
        int r = f / L_CELLS, c = f - (f / L_CELLS) * L_CELLS;
        float2 v = __ldg(reinterpret_cast<const float2*>(
            preds + (size_t)(row0 + r) * ROW_P + 980) + c);
        s_conf[r * 2 * L_CELLS + 2 * c]     = v.x;
        s_conf[r * 2 * L_CELLS + 2 * c + 1] = v.y;
    }
    __syncthreads();

    // ===== per-cell: noobj base + ballot compaction =========================
    float vbase = 0.0f;
    unsigned bal[NITER];
    int T = 0;
    #pragma unroll
    for (int k = 0; k < NITER; k++) {
        int cell = k * THREADS + tid;
        bool valid = cell < ncell;
        bool objf  = false;
        if (valid) {
            int r = cell / L_CELLS, l = cell - (cell / L_CELLS) * L_CELLS;
            float cx = s_conf[r * 2 * L_CELLS + 2 * l];
            float cy = s_conf[r * 2 * L_CELLS + 2 * l + 1];
            vbase += NOOBJ_W * (cx * cx + cy * cy);
            objf = (s_lab[r * ROW_L + 25 * l] != 0.0f);
        }
        bal[k] = __ballot_sync(0xffffffffu, objf);
        T += __popc(bal[k]);
    }

    // ===== per-warp obj walk (no barriers) ===================================
    const int wbase = wid * 32;
    double vd = (double)vbase;
    for (int t = lane; t < T; t += 32) {
        int j = t;
        int cellLocal = 0;
        #pragma unroll
        for (int k = 0; k < NITER; k++) {
            int c = __popc(bal[k]);
            if (j >= 0 && j < c) {
                int pos = __fns(bal[k], 0, j + 1);
                cellLocal = k * THREADS + wbase + pos;
            }
            j -= c;
        }
        vd += (double)obj_cell_loss(preds, s_lab, s_conf, row0, cellLocal);
    }

    // ===== block reduction ===================================================
    #pragma unroll
    for (int off = 16; off > 0; off >>= 1)
        vd += __shfl_down_sync(0xffffffffu, vd, off);
    if (lane == 0) s_red[wid] = vd;
    __syncthreads();

    if (wid == 0) {
        double x = (lane < NWARPS) ? s_red[lane] : 0.0;
        #pragma unroll
        for (int off = 4; off > 0; off >>= 1)
            x += __shfl_down_sync(0xffffffffu, x, off);
        if (lane == 0) g_partials[blockIdx.x] = x;
    }
    __syncthreads();

    // ===== fused finalize: last block reduces all partials ===================
    if (tid == 0) {
        __threadfence();
        unsigned old = atomicInc(&g_counter, gridDim.x - 1);
        s_last = (old == gridDim.x - 1);
    }
    __syncthreads();

    if (s_last) {
        __threadfence();
        double s = 0.0;
        for (int i = tid; i < gridDim.x; i += THREADS)
            s += g_partials[i];
        #pragma unroll
        for (int off = 16; off > 0; off >>= 1)
            s += __shfl_down_sync(0xffffffffu, s, off);
        if (lane == 0) s_red[wid] = s;
        __syncthreads();
        if (wid == 0) {
            double x = (lane < NWARPS) ? s_red[lane] : 0.0;
            #pragma unroll
            for (int off = 4; off > 0; off >>= 1)
                x += __shfl_down_sync(0xffffffffu, x, off);
            if (lane == 0) out[0] = (float)x;
        }
    }
}

extern "C" void kernel_launch(void* const* d_in, const int* in_sizes, int n_in,
                              void* d_out, int out_size)
{
    const float* preds  = (const float*)d_in[0];
    const float* labels = (const float*)d_in[1];
    int n = in_sizes[0] / ROW_P;

    int blocks = (n + RPB - 1) / RPB;   // n=16384 -> 2048 blocks
    if (blocks > MAX_BLOCKS) blocks = MAX_BLOCKS;

    yolo_loss_kernel<<<blocks, THREADS>>>(preds, labels, n, (float*)d_out);
}

// round 11
// speedup vs baseline: 1.9583x; 1.9583x over previous
#include <cuda_runtime.h>

// YOLO-style detection loss — R7 structure, 128-thread blocks for occupancy.
// preds:  (n, 1470) f32  [pcls 980 | pconf 98 | pbox 392]
// labels: (n, 1225) f32  per cell (25 floats): [flag | 20 cls | 4 box]
// Row bases only 8B-aligned for odd rows => vector loads are float2 max.

#define L_CELLS 49
#define ROW_P 1470
#define ROW_L 1225
#define NOOBJ_W 0.5f
#define OBJ_W 0.5f
#define CLS_W 0.5f
#define COORD_W 2.5f

#define THREADS 128
#define CPT 4
#define CPB (THREADS * CPT)           // 512 cells/block -> 1568 blocks
#define NWARPS (THREADS / 32)
#define MAX_BLOCKS 32768

__device__ double   g_partials[MAX_BLOCKS];
__device__ unsigned g_counter = 0;    // self-wrapping; replay-safe

__device__ __forceinline__ float obj_cell_loss(
    const float* __restrict__ preds,
    const float* __restrict__ labels,
    int cell)
{
    int i = cell / L_CELLS;
    int l = cell - i * L_CELLS;
    const float* p  = preds  + (size_t)i * ROW_P;
    const float* lb = labels + (size_t)i * ROW_L + l * 25;

    // ---- issue all loads up front ----
    float2 pc = __ldg(reinterpret_cast<const float2*>(p + 980 + l * 2));

    float tb0 = __ldg(lb + 21);
    float tb1 = __ldg(lb + 22);
    float tb2 = __ldg(lb + 23);
    float tb3 = __ldg(lb + 24);

    const float* pb = p + 1078 + l * 8;       // 8B aligned
    float2 b01 = __ldg(reinterpret_cast<const float2*>(pb + 0));
    float2 b23 = __ldg(reinterpret_cast<const float2*>(pb + 2));
    float2 b45 = __ldg(reinterpret_cast<const float2*>(pb + 4));
    float2 b67 = __ldg(reinterpret_cast<const float2*>(pb + 6));

    // ---- class loss (float2 only; l*20 even -> 8B aligned) ----
    const float* pcl = p + l * 20;
    float cls = 0.0f;
    #pragma unroll
    for (int c = 0; c < 20; c += 2) {
        float2 pv = __ldg(reinterpret_cast<const float2*>(pcl + c));
        float d0 = __ldg(lb + 1 + c) - pv.x;
        float d1 = __ldg(lb + 2 + c) - pv.y;
        cls += d0 * d0 + d1 * d1;
    }
    cls *= CLS_W;

    // transformed: o = [x/S, y/S, w^2, h^2]; t = [x/S, y/S, w, h]
    float o0x = b01.x * (1.0f / 7.0f), o0y = b01.y * (1.0f / 7.0f);
    float o0w = b23.x * b23.x,         o0h = b23.y * b23.y;
    float o1x = b45.x * (1.0f / 7.0f), o1y = b45.y * (1.0f / 7.0f);
    float o1w = b67.x * b67.x,         o1h = b67.y * b67.y;
    float tx = tb0 * (1.0f / 7.0f), ty = tb1 * (1.0f / 7.0f);
    float tw = tb2, th = tb3;

    float iou0, iou1, r0, r1;
    {
        float left   = fmaxf(tx - 0.5f * tw, o0x - 0.5f * o0w);
        float right  = fminf(tx + 0.5f * tw, o0x + 0.5f * o0w);
        float top    = fmaxf(ty - 0.5f * th, o0y - 0.5f * o0h);
        float bottom = fminf(ty + 0.5f * th, o0y + 0.5f * o0h);
        float w = right - left, h = bottom - top;
        bool invalid = (w < 0.0f) || (h < 0.0f);
        float inter = invalid ? 0.0f : w * h;
        float uni = tw * th + o0w * o0h - inter;
        iou0 = invalid ? 0.0f : inter / fmaxf(uni, 1e-12f);
        float d0 = tx - o0x, d1 = ty - o0y, d2 = tw - o0w, d3 = th - o0h;
        r0 = d0 * d0 + d1 * d1 + d2 * d2 + d3 * d3;
    }
    {
        float left   = fmaxf(tx - 0.5f * tw, o1x - 0.5f * o1w);
        float right  = fminf(tx + 0.5f * tw, o1x + 0.5f * o1w);
        float top    = fmaxf(ty - 0.5f * th, o1y - 0.5f * o1h);
        float bottom = fminf(ty + 0.5f * th, o1y + 0.5f * o1h);
        float w = right - left, h = bottom - top;
        bool invalid = (w < 0.0f) || (h < 0.0f);
        float inter = invalid ? 0.0f : w * h;
        float uni = tw * th + o1w * o1h - inter;
        iou1 = invalid ? 0.0f : inter / fmaxf(uni, 1e-12f);
        float d0 = tx - o1x, d1 = ty - o1y, d2 = tw - o1w, d3 = th - o1h;
        r1 = d0 * d0 + d1 * d1 + d2 * d2 + d3 * d3;
    }

    // argmax/argmin first-index tie semantics
    float miou = fmaxf(iou0, iou1);
    int best = (miou > 0.0f) ? ((iou1 > iou0) ? 1 : 0)
                             : ((r1 < r0) ? 1 : 0);

    float best_iou  = best ? iou1 : iou0;
    float conf_best = best ? pc.y : pc.x;
    float dcb = best_iou - conf_best;
    // correction vs unconditional NOOBJ*(cx^2+cy^2) base from phase 1
    float conf_corr = OBJ_W * dcb * dcb - NOOBJ_W * conf_best * conf_best;

    float pbx = best ? b45.x : b01.x;
    float pby = best ? b45.y : b01.y;
    float pbw = best ? b67.x : b23.x;
    float pbh = best ? b67.y : b23.y;
    float st2 = sqrtf(tb2), st3 = sqrtf(tb3);
    float e0 = tb0 - pbx, e1 = tb1 - pby;
    float e2 = st2 - pbw, e3 = st3 - pbh;
    float coord = COORD_W * (e0 * e0 + e1 * e1 + e2 * e2 + e3 * e3);

    return conf_corr + cls + coord;
}

__global__ void __launch_bounds__(THREADS) yolo_loss_kernel(
    const float* __restrict__ preds,
    const float* __restrict__ labels,
    int total_cells,
    float* __restrict__ out)
{
    __shared__ double s_red[NWARPS];
    __shared__ bool   s_last;

    const int tid  = threadIdx.x;
    const int lane = tid & 31;
    const int wid  = tid >> 5;
    const int base = blockIdx.x * CPB;
    const int wbase = wid * 32;

    // ===== phase 1: flags + pconf, front-batched (MLP = 8) ==================
    float  flag[CPT];
    float2 pc[CPT];
    bool   valid[CPT];

    #pragma unroll
    for (int k = 0; k < CPT; k++) {
        int cell = base + k * THREADS + tid;
        valid[k] = cell < total_cells;
        int c = valid[k] ? cell : 0;
        int i = c / L_CELLS, l = c - (c / L_CELLS) * L_CELLS;
        flag[k] = __ldg(labels + (size_t)i * ROW_L + 25 * l);
        pc[k]   = __ldg(reinterpret_cast<const float2*>(
                        preds + (size_t)i * ROW_P + 980 + 2 * l));
    }

    float vbase = 0.0f;
    unsigned bal[CPT];
    int T = 0;
    #pragma unroll
    for (int k = 0; k < CPT; k++) {
        if (valid[k])
            vbase += NOOBJ_W * (pc[k].x * pc[k].x + pc[k].y * pc[k].y);
        bal[k] = __ballot_sync(0xffffffffu, valid[k] && (flag[k] != 0.0f));
        T += __popc(bal[k]);
    }

    // ===== phase 2: per-warp obj processing (no barriers, no smem) ==========
    double vd = (double)vbase;
    for (int t = lane; t < T; t += 32) {
        int j = t;
        int cellLocal = 0;
        #pragma unroll
        for (int k = 0; k < CPT; k++) {
            int c = __popc(bal[k]);
            if (j >= 0 && j < c) {
                int pos = __fns(bal[k], 0, j + 1);
                cellLocal = k * THREADS + wbase + pos;
            }
            j -= c;
        }
        vd += (double)obj_cell_loss(preds, labels, base + cellLocal);
    }

    // ===== block reduction ===================================================
    #pragma unroll
    for (int off = 16; off > 0; off >>= 1)
        vd += __shfl_down_sync(0xffffffffu, vd, off);
    if (lane == 0) s_red[wid] = vd;
    __syncthreads();

    if (wid == 0) {
        double x = (lane < NWARPS) ? s_red[lane] : 0.0;
        #pragma unroll
        for (int off = 2; off > 0; off >>= 1)
            x += __shfl_down_sync(0xffffffffu, x, off);
        if (lane == 0) g_partials[blockIdx.x] = x;
    }
    __syncthreads();

    // ===== fused finalize: last block reduces all partials ===================
    if (tid == 0) {
        __threadfence();
        unsigned old = atomicInc(&g_counter, gridDim.x - 1);
        s_last = (old == gridDim.x - 1);
    }
    __syncthreads();

    if (s_last) {
        __threadfence();
        double s = 0.0;
        for (int i = tid; i < gridDim.x; i += THREADS)
            s += g_partials[i];
        #pragma unroll
        for (int off = 16; off > 0; off >>= 1)
            s += __shfl_down_sync(0xffffffffu, s, off);
        if (lane == 0) s_red[wid] = s;
        __syncthreads();
        if (wid == 0) {
            double x = (lane < NWARPS) ? s_red[lane] : 0.0;
            #pragma unroll
            for (int off = 2; off > 0; off >>= 1)
                x += __shfl_down_sync(0xffffffffu, x, off);
            if (lane == 0) out[0] = (float)x;
        }
    }
}

extern "C" void kernel_launch(void* const* d_in, const int* in_sizes, int n_in,
                              void* d_out, int out_size)
{
    const float* preds  = (const float*)d_in[0];
    const float* labels = (const float*)d_in[1];
    int n = in_sizes[0] / ROW_P;
    int total_cells = n * L_CELLS;

    int blocks = (total_cells + CPB - 1) / CPB;   // n=16384 -> 1568 blocks
    if (blocks > MAX_BLOCKS) blocks = MAX_BLOCKS;

    yolo_loss_kernel<<<blocks, THREADS>>>(preds, labels, total_cells,
                                          (float*)d_out);
}